// round 14
// baseline (speedup 1.0000x reference)
#include <cuda_runtime.h>
#include <cuda_bf16.h>
#include <cstdint>

#define BATCH   4096
#define NB      64
#define IN_DIM  256
#define NTOT    4096
#define DT_C    0.05f
#define TAU_EPS 1e-6f

// bf16 tile row pitch: 72 elems = 144 bytes (odd 16B-groups -> conflict-free ldmatrix)
#define PITCH   144

// ---------------- ltc_main SMEM layout (byte offsets) ----------------
#define A0_OFF  0                       // 128 x 64 bf16 (y_prev | net0)
#define A1_OFF  18432                   // 128 x 64 bf16 (y_cur)
#define W0_OFF  36864                   // W_fwd[j-1]
#define W1_OFF  46080                   // W_rec[j]
#define W2_OFF  55296                   // E_l[j]
#define W3_OFF  64512                   // E_l_r[j]
#define BR_OFF  73728
#define BF_OFF  (BR_OFF + 256)
#define IT_OFF  (BF_OFF + 256)
#define SMEM_TOTAL (IT_OFF + 256)       // 74496 B; occupancy pinned to 2 CTAs/SM

// ---------------- prep-kernel net0 SMEM layout ----------------
#define N0_PITCH 528                    // 256 bf16 = 512B + 16B pad
#define N0_U_OFF 0
#define N0_W_OFF 33792
#define N0_B_OFF 67584
#define N0_SMEM  (N0_B_OFF + 256)

// ---------------- device-global staging buffers ----------------
// concatenated bf16 weights: [Wf 63 tiles][Wr 64][El 64][Elr 64] = 255 tiles
__device__ __nv_bfloat16 g_wbf[255 * 4096];
__device__ __nv_bfloat16 g_net0bf[BATCH * 64];
__device__ float         g_itau[NTOT];

#define WFB_OFF   0
#define WRB_OFF   (63 * 4096)
#define ELB_OFF   (127 * 4096)
#define ELRB_OFF  (191 * 4096)

// ---------------------------------------------------------------------------
// helpers
// ---------------------------------------------------------------------------
__device__ __forceinline__ uint32_t smem_u32(const void* p) {
    uint32_t a;
    asm("{ .reg .u64 t; cvta.to.shared.u64 t, %1; cvt.u32.u64 %0, t; }"
        : "=r"(a) : "l"(p));
    return a;
}
__device__ __forceinline__ float tanh_fast(float x) {
    float r; asm("tanh.approx.f32 %0, %1;" : "=f"(r) : "f"(x)); return r;
}
__device__ __forceinline__ uint32_t bf2(float lo, float hi) {
    uint32_t r;
    asm("cvt.rn.bf16x2.f32 %0, %1, %2;" : "=r"(r) : "f"(hi), "f"(lo));
    return r;
}
__device__ __forceinline__ float2 ubf2(uint32_t v) {
    __nv_bfloat162 b = *reinterpret_cast<__nv_bfloat162*>(&v);
    return __bfloat1622float2(b);
}
__device__ __forceinline__ void stcs2(float* p, float2 v) {
    asm volatile("st.global.cs.v2.f32 [%0], {%1, %2};"
                 :: "l"(p), "f"(v.x), "f"(v.y) : "memory");
}
__device__ __forceinline__ void cpa16(uint32_t dst, const void* src) {
    asm volatile("cp.async.cg.shared.global [%0], [%1], 16;"
                 :: "r"(dst), "l"(src) : "memory");
}

#define LDM4(r, addr) \
    asm volatile("ldmatrix.sync.aligned.m8n8.x4.shared.b16 {%0,%1,%2,%3}, [%4];" \
        : "=r"((r)[0]), "=r"((r)[1]), "=r"((r)[2]), "=r"((r)[3]) : "r"(addr))

__device__ __forceinline__ void mma16816(float* c, const uint32_t* a,
                                         uint32_t b0, uint32_t b1) {
    asm volatile(
        "mma.sync.aligned.m16n8k16.row.col.f32.bf16.bf16.f32 "
        "{%0,%1,%2,%3}, {%4,%5,%6,%7}, {%8,%9}, {%0,%1,%2,%3};"
        : "+f"(c[0]), "+f"(c[1]), "+f"(c[2]), "+f"(c[3])
        : "r"(a[0]), "r"(a[1]), "r"(a[2]), "r"(a[3]), "r"(b0), "r"(b1));
}

// Warp computes C[32 x 64] += A_smem[32 x 64] * W_smem[64 x 64]^T
__device__ __forceinline__ void gemm32x64(uint32_t abase, uint32_t wbase,
                                          float acc[16][4], int lane, int warpM)
{
    uint32_t pa = abase + (uint32_t)((warpM + (lane & 7) + ((lane >> 3) & 1) * 8) * PITCH
                                     + ((lane >> 4) * 8) * 2);
    uint32_t pb = wbase + (uint32_t)((((lane & 7) + ((lane >> 4) & 1) * 8)) * PITCH
                                     + (((lane >> 3) & 1) * 8) * 2);
#pragma unroll
    for (int ks = 0; ks < 4; ks++) {
        uint32_t a0[4], a1[4];
        LDM4(a0, pa + ks * 32);
        LDM4(a1, pa + 16 * PITCH + ks * 32);
#pragma unroll
        for (int np = 0; np < 4; np++) {
            uint32_t b[4];
            LDM4(b, pb + np * 16 * PITCH + ks * 32);
            mma16816(acc[np * 2 + 0],     a0, b[0], b[1]);
            mma16816(acc[np * 2 + 1],     a0, b[2], b[3]);
            mma16816(acc[8 + np * 2 + 0], a1, b[0], b[1]);
            mma16816(acc[8 + np * 2 + 1], a1, b[2], b[3]);
        }
    }
}

// Load A-fragments (packed bf16x2 lo/hi layout) for warp's 32 rows from smem tile
__device__ __forceinline__ void load_fragsA(uint32_t abase,
                                            uint32_t lo[2][8], uint32_t hi[2][8],
                                            int lane, int warpM)
{
    uint32_t pa = abase + (uint32_t)((warpM + (lane & 7) + ((lane >> 3) & 1) * 8) * PITCH
                                     + ((lane >> 4) * 8) * 2);
#pragma unroll
    for (int ks = 0; ks < 4; ks++) {
        uint32_t a0[4], a1[4];
        LDM4(a0, pa + ks * 32);
        LDM4(a1, pa + 16 * PITCH + ks * 32);
        lo[0][2 * ks] = a0[0]; hi[0][2 * ks] = a0[1];
        lo[0][2 * ks + 1] = a0[2]; hi[0][2 * ks + 1] = a0[3];
        lo[1][2 * ks] = a1[0]; hi[1][2 * ks] = a1[1];
        lo[1][2 * ks + 1] = a1[2]; hi[1][2 * ks + 1] = a1[3];
    }
}

// Fused phase-2: C[32 x 64] += NO_regs * W2^T + NR_regs * W3^T
__device__ __forceinline__ void gemm32x64_reg2(uint32_t w2base, uint32_t w3base,
                                               const uint32_t no_lo[2][8],
                                               const uint32_t no_hi[2][8],
                                               const uint32_t nr_lo[2][8],
                                               const uint32_t nr_hi[2][8],
                                               float acc[16][4], int lane)
{
    uint32_t boff = (uint32_t)((((lane & 7) + ((lane >> 4) & 1) * 8)) * PITCH
                               + (((lane >> 3) & 1) * 8) * 2);
    uint32_t pb2 = w2base + boff;
    uint32_t pb3 = w3base + boff;
#pragma unroll
    for (int ks = 0; ks < 4; ks++) {
#pragma unroll
        for (int np = 0; np < 4; np++) {
            uint32_t b2[4], b3[4];
            LDM4(b2, pb2 + np * 16 * PITCH + ks * 32);
            LDM4(b3, pb3 + np * 16 * PITCH + ks * 32);
#pragma unroll
            for (int mt = 0; mt < 2; mt++) {
                uint32_t an[4] = { no_lo[mt][2 * ks], no_hi[mt][2 * ks],
                                   no_lo[mt][2 * ks + 1], no_hi[mt][2 * ks + 1] };
                uint32_t ar[4] = { nr_lo[mt][2 * ks], nr_hi[mt][2 * ks],
                                   nr_lo[mt][2 * ks + 1], nr_hi[mt][2 * ks + 1] };
                mma16816(acc[mt * 8 + np * 2 + 0], an, b2[0], b2[1]);
                mma16816(acc[mt * 8 + np * 2 + 1], an, b2[2], b2[3]);
                mma16816(acc[mt * 8 + np * 2 + 0], ar, b3[0], b3[1]);
                mma16816(acc[mt * 8 + np * 2 + 1], ar, b3[2], b3[3]);
            }
        }
    }
}

// tanh(acc + bias) -> packed bf16x2 fragments in registers
__device__ __forceinline__ void pack_tanh(const float acc[16][4], const float* bias,
                                          uint32_t lo[2][8], uint32_t hi[2][8],
                                          int lane)
{
    const int nb = (lane & 3) * 2;
#pragma unroll
    for (int mt = 0; mt < 2; mt++)
#pragma unroll
        for (int nt = 0; nt < 8; nt++) {
            const float* c = acc[mt * 8 + nt];
            float b0 = bias[nt * 8 + nb], b1 = bias[nt * 8 + nb + 1];
            lo[mt][nt] = bf2(tanh_fast(c[0] + b0), tanh_fast(c[1] + b1));
            hi[mt][nt] = bf2(tanh_fast(c[2] + b0), tanh_fast(c[3] + b1));
        }
}

__device__ __forceinline__ void zero_acc(float acc[16][4]) {
#pragma unroll
    for (int i = 0; i < 16; i++)
#pragma unroll
        for (int q = 0; q < 4; q++) acc[i][q] = 0.f;
}

// fp32 -> bf16 staging of a 128x64 tile (row stride srcPitch) into PITCH layout
__device__ __forceinline__ void stage128(char* dst, const float* __restrict__ src,
                                         int srcPitch, int t)
{
#pragma unroll
    for (int i = 0; i < 16; i++) {
        int idx = t + i * 128;
        int r = idx >> 4, c4 = idx & 15;
        float4 v = *(const float4*)&src[r * srcPitch + c4 * 4];
        *(uint2*)(dst + r * PITCH + c4 * 8) = make_uint2(bf2(v.x, v.y), bf2(v.z, v.w));
    }
}

// cp.async a 64x128B bf16 tile (contiguous in global) into PITCH layout
__device__ __forceinline__ void stage_w_cp(uint32_t dstbase,
                                           const __nv_bfloat16* __restrict__ src,
                                           int t)
{
#pragma unroll
    for (int c = 0; c < 4; c++) {
        int ch = t * 4 + c;                 // 512 chunks of 16B
        int row = ch >> 3, col = ch & 7;
        cpa16(dstbase + row * PITCH + col * 16, (const char*)src + ch * 16);
    }
}

// ---------------------------------------------------------------------------
// Prep kernel: weight fp32->bf16 convert + itau + net0 (bf16).
// grid 320 x 256 threads.
// ---------------------------------------------------------------------------
__global__ void __launch_bounds__(256) prep_kernel(
    const float* __restrict__ u,
    const float* __restrict__ tau_raw,
    const float* __restrict__ Wi,  const float* __restrict__ bi,
    const float* __restrict__ Wf,  const float* __restrict__ Wr,
    const float* __restrict__ El,  const float* __restrict__ Elr)
{
    extern __shared__ char sm[];
    const int bx = blockIdx.x;
    const int t  = threadIdx.x;

    if (bx < 255) {
        // convert one 64x64 weight tile to bf16
        const float* src;
        if (bx < 63)       src = Wf  + bx * 4096;
        else if (bx < 127) src = Wr  + (bx - 63) * 4096;
        else if (bx < 191) src = El  + (bx - 127) * 4096;
        else               src = Elr + (bx - 191) * 4096;
        __nv_bfloat16* dst = g_wbf + bx * 4096;
#pragma unroll
        for (int c = 0; c < 4; c++) {
            int i = (t + c * 256) * 4;
            float4 v = *(const float4*)&src[i];
            *(uint2*)&dst[i] = make_uint2(bf2(v.x, v.y), bf2(v.z, v.w));
        }
    } else if (bx == 255) {
        for (int i = t; i < NTOT; i += 256) {
            float x  = tau_raw[i];
            float sp = (x > 20.f) ? x : log1pf(expf(x));
            g_itau[i] = 1.0f / (sp + TAU_EPS);
        }
    } else {
        // net0 for batch tile bt (64 rows), via bf16 mma over K=256
        const int bt   = bx - 256;
        const int lane = t & 31;
        const int w    = t >> 5;
        const uint32_t smb = smem_u32(sm);
        float* s_bi = (float*)(sm + N0_B_OFF);

#pragma unroll
        for (int i = 0; i < 16; i++) {
            int idx = t + i * 256;
            int r = idx >> 6, c4 = idx & 63;
            float4 v = *(const float4*)&u[(bt * 64 + r) * IN_DIM + c4 * 4];
            *(uint2*)(sm + N0_U_OFF + r * N0_PITCH + c4 * 8) =
                make_uint2(bf2(v.x, v.y), bf2(v.z, v.w));
            float4 wv = *(const float4*)&Wi[r * IN_DIM + c4 * 4];
            *(uint2*)(sm + N0_W_OFF + r * N0_PITCH + c4 * 8) =
                make_uint2(bf2(wv.x, wv.y), bf2(wv.z, wv.w));
        }
        if (t < 64) s_bi[t] = bi[t];
        __syncthreads();

        if (w < 4) {
            float acc[8][4];
#pragma unroll
            for (int i = 0; i < 8; i++)
#pragma unroll
                for (int q = 0; q < 4; q++) acc[i][q] = 0.f;

            uint32_t pa = smb + N0_U_OFF +
                (uint32_t)((w * 16 + (lane & 7) + ((lane >> 3) & 1) * 8) * N0_PITCH
                           + (lane >> 4) * 16);
            uint32_t pb = smb + N0_W_OFF +
                (uint32_t)((((lane & 7) + ((lane >> 4) & 1) * 8)) * N0_PITCH
                           + ((lane >> 3) & 1) * 16);
#pragma unroll
            for (int ks = 0; ks < 16; ks++) {
                uint32_t a[4];
                LDM4(a, pa + ks * 32);
#pragma unroll
                for (int np = 0; np < 4; np++) {
                    uint32_t b[4];
                    LDM4(b, pb + np * 16 * N0_PITCH + ks * 32);
                    mma16816(acc[np * 2 + 0], a, b[0], b[1]);
                    mma16816(acc[np * 2 + 1], a, b[2], b[3]);
                }
            }

            const int gml = w * 16 + (lane >> 2);
            const int nb  = (lane & 3) * 2;
#pragma unroll
            for (int nt = 0; nt < 8; nt++) {
                int n = nt * 8 + nb;
                float b0 = s_bi[n], b1 = s_bi[n + 1];
                const float* c = acc[nt];
                int row = bt * 64 + gml;
                *(uint32_t*)&g_net0bf[row * 64 + n] =
                    bf2(tanh_fast(c[0] + b0), tanh_fast(c[1] + b1));
                *(uint32_t*)&g_net0bf[(row + 8) * 64 + n] =
                    bf2(tanh_fast(c[2] + b0), tanh_fast(c[3] + b1));
            }
        }
    }
}

// ---------------------------------------------------------------------------
// Main kernel. grid (32 batch tiles, 64 blocks j), 128 threads.
// ---------------------------------------------------------------------------
__global__ void __launch_bounds__(128, 2) ltc_main(
    const float* __restrict__ y,
    const float* __restrict__ bfw,
    const float* __restrict__ brw,
    float* __restrict__ out)
{
    extern __shared__ char sm[];
    const int t     = threadIdx.x;
    const int lane  = t & 31;
    const int warpM = (t >> 5) * 32;
    const int bt    = blockIdx.x;
    const int j     = blockIdx.y;
    const int row0  = bt * 128;

    float* s_br = (float*)(sm + BR_OFF);
    float* s_bf = (float*)(sm + BF_OFF);
    float* s_it = (float*)(sm + IT_OFF);
    const uint32_t smb = smem_u32(sm);

    // ---------------- cp.async weight tiles (pre-converted bf16) ----------
    stage_w_cp(smb + W1_OFF, g_wbf + WRB_OFF  + j * 4096, t);
    stage_w_cp(smb + W2_OFF, g_wbf + ELB_OFF  + j * 4096, t);
    stage_w_cp(smb + W3_OFF, g_wbf + ELRB_OFF + j * 4096, t);
    if (j > 0) {
        stage_w_cp(smb + W0_OFF, g_wbf + WFB_OFF + (j - 1) * 4096, t);
    } else {
        // A0 <- precomputed net0 tile (128 rows x 128B)
#pragma unroll
        for (int c = 0; c < 8; c++) {
            int ch = t * 8 + c;
            int row = ch >> 3, col = ch & 7;
            cpa16(smb + A0_OFF + row * PITCH + col * 16,
                  (const char*)(g_net0bf + (size_t)row0 * 64) + ch * 16);
        }
    }

    // ---------------- fp32 y staging (cvt path) ----------------
    stage128(sm + A1_OFF, y + (size_t)row0 * NTOT + j * 64, NTOT, t);
    if (j > 0)
        stage128(sm + A0_OFF, y + (size_t)row0 * NTOT + (j - 1) * 64, NTOT, t);
    if (t < 64) {
        s_br[t] = brw[j * 64 + t];
        if (j > 0) s_bf[t] = bfw[(j - 1) * 64 + t];
        s_it[t] = g_itau[j * 64 + t];
    }
    asm volatile("cp.async.commit_group;\n\tcp.async.wait_group 0;" ::: "memory");
    __syncthreads();

    float acc[16][4];
    uint32_t nr_lo[2][8], nr_hi[2][8];   // net_rec packed bf16x2 fragments
    uint32_t no_lo[2][8], no_hi[2][8];   // net_out packed bf16x2 fragments

    // ---------------- Phase 1a: net_rec = tanh(y_cur @ Wr^T + br) ----------
    zero_acc(acc);
    gemm32x64(smb + A1_OFF, smb + W1_OFF, acc, lane, warpM);
    pack_tanh(acc, s_br, nr_lo, nr_hi, lane);

    // ---------------- Phase 1b: net_out ------------------------------------
    if (j > 0) {
        zero_acc(acc);
        gemm32x64(smb + A0_OFF, smb + W0_OFF, acc, lane, warpM);
        pack_tanh(acc, s_bf, no_lo, no_hi, lane);
    } else {
        load_fragsA(smb + A0_OFF, no_lo, no_hi, lane, warpM);
    }

    // ---------------- Phase 2: drive = net_out@El^T + net_rec@Elr^T --------
    zero_acc(acc);
    gemm32x64_reg2(smb + W2_OFF, smb + W3_OFF,
                   no_lo, no_hi, nr_lo, nr_hi, acc, lane);

    // ---------------- Epilogue: combine + direct fragment I/O --------------
    {
        const int gm = warpM + (lane >> 2);
        const int nb = (lane & 3) * 2;
#pragma unroll
        for (int mt = 0; mt < 2; mt++)
#pragma unroll
            for (int nt = 0; nt < 8; nt++) {
                int n = nt * 8 + nb;
                float it0 = s_it[n], it1 = s_it[n + 1];
                float2 no0 = ubf2(no_lo[mt][nt]), no1 = ubf2(no_hi[mt][nt]);
                float2 nr0 = ubf2(nr_lo[mt][nt]), nr1 = ubf2(nr_hi[mt][nt]);
                const float* c = acc[mt * 8 + nt];
                int m0 = gm + mt * 16;
                size_t g0 = (size_t)(row0 + m0) * NTOT + j * 64 + n;
                size_t g1 = (size_t)(row0 + m0 + 8) * NTOT + j * 64 + n;
                float2 ya = __ldg((const float2*)&y[g0]);
                float2 yc = __ldg((const float2*)&y[g1]);
                float2 o0, o1;
                o0.x = __fdividef(ya.x + DT_C * c[0],
                                  1.f + DT_C * (it0 + fabsf(no0.x) + fabsf(nr0.x)));
                o0.y = __fdividef(ya.y + DT_C * c[1],
                                  1.f + DT_C * (it1 + fabsf(no0.y) + fabsf(nr0.y)));
                o1.x = __fdividef(yc.x + DT_C * c[2],
                                  1.f + DT_C * (it0 + fabsf(no1.x) + fabsf(nr1.x)));
                o1.y = __fdividef(yc.y + DT_C * c[3],
                                  1.f + DT_C * (it1 + fabsf(no1.y) + fabsf(nr1.y)));
                stcs2(&out[g0], o0);
                stcs2(&out[g1], o1);
            }
    }
}

// ---------------------------------------------------------------------------
extern "C" void kernel_launch(void* const* d_in, const int* in_sizes, int n_in,
                              void* d_out, int out_size) {
    const float* y   = (const float*)d_in[0];
    const float* u_t = (const float*)d_in[1];
    const float* tau = (const float*)d_in[2];
    const float* Wi  = (const float*)d_in[3];
    const float* bi  = (const float*)d_in[4];
    const float* Wf  = (const float*)d_in[5];
    const float* bfw = (const float*)d_in[6];
    const float* Wr  = (const float*)d_in[7];
    const float* brw = (const float*)d_in[8];
    const float* El  = (const float*)d_in[9];
    const float* Elr = (const float*)d_in[10];
    float* out = (float*)d_out;

    cudaFuncSetAttribute(prep_kernel, cudaFuncAttributeMaxDynamicSharedMemorySize,
                         N0_SMEM);
    cudaFuncSetAttribute(ltc_main, cudaFuncAttributeMaxDynamicSharedMemorySize,
                         SMEM_TOTAL);

    prep_kernel<<<320, 256, N0_SMEM>>>(u_t, tau, Wi, bi, Wf, Wr, El, Elr);
    ltc_main<<<dim3(BATCH / 128, NB), 128, SMEM_TOTAL>>>(y, bfw, brw, out);
}